// round 1
// baseline (speedup 1.0000x reference)
#include <cuda_runtime.h>
#include <cuda_fp16.h>
#include <cstdint>

#define NN 4096   // nodes
#define DD 128    // embed dim
#define RR 8      // relations
#define OO 128    // out dim
#define BB 4096   // batch

// Scratch: W[r][n][o] = sum_d E[n][d] * K[r][d][o], stored fp16, 8 MB.
__device__ __half d_W16[RR * (size_t)NN * OO];

// ---------------------------------------------------------------------------
// Kernel 1: out = e @ self_kernel  (writes base values; d_out is poisoned)
// grid: (128 row-tiles, 2 branches), 256 threads
// ---------------------------------------------------------------------------
__global__ __launch_bounds__(256) void init_kernel(
    const float* __restrict__ head_e, const float* __restrict__ tail_e,
    const float* __restrict__ sk, float* __restrict__ out)
{
    __shared__ float Es[32][DD];                    // 16 KB
    const int t = threadIdx.x;
    const int n0 = blockIdx.x * 32;
    const int branch = blockIdx.y;
    const float* e = branch ? tail_e : head_e;

#pragma unroll
    for (int j = 0; j < 4; j++) {
        int id = t + j * 256;
        int row = id >> 5, c = id & 31;
        *(float4*)&Es[row][c * 4] =
            *(const float4*)(e + (size_t)(n0 + row) * DD + c * 4);
    }
    __syncthreads();

    const int o = t & 127;
    const int hf = t >> 7;                          // 0..1 -> 16 rows each
    float acc[16];
#pragma unroll
    for (int i = 0; i < 16; i++) acc[i] = 0.f;

    for (int d = 0; d < DD; d++) {
        float skv = sk[d * OO + o];
#pragma unroll
        for (int i = 0; i < 16; i++)
            acc[i] = fmaf(Es[hf * 16 + i][d], skv, acc[i]);
    }
    float* ob = out + (size_t)branch * BB * OO;
#pragma unroll
    for (int i = 0; i < 16; i++)
        ob[(size_t)(n0 + hf * 16 + i) * OO + o] = acc[i];
}

// ---------------------------------------------------------------------------
// Kernel 2: W16[r][n][o] = (E @ K[r])[n][o], fp32 accumulate, fp16 store
// grid: (64 n-tiles, 8 relations), 256 threads
// ---------------------------------------------------------------------------
__global__ __launch_bounds__(256) void w_kernel(
    const float* __restrict__ emb, const float* __restrict__ relk)
{
    __shared__ float Es[64][DD];                    // 32 KB
    const int t = threadIdx.x;
    const int n0 = blockIdx.x * 64;
    const int r = blockIdx.y;

#pragma unroll
    for (int j = 0; j < 8; j++) {
        int id = t + j * 256;
        int row = id >> 5, c = id & 31;
        *(float4*)&Es[row][c * 4] =
            *(const float4*)(emb + (size_t)(n0 + row) * DD + c * 4);
    }
    __syncthreads();

    const int og = t & 31;                          // o = og*4 .. +3
    const int ng = t >> 5;                          // rows ng*8 .. +7
    const float* Kr = relk + (size_t)r * DD * OO;

    float acc[8][4];
#pragma unroll
    for (int i = 0; i < 8; i++)
#pragma unroll
        for (int j = 0; j < 4; j++) acc[i][j] = 0.f;

    for (int d = 0; d < DD; d++) {
        float4 kv = *((const float4*)(Kr + (size_t)d * OO) + og);
#pragma unroll
        for (int i = 0; i < 8; i++) {
            float ev = Es[ng * 8 + i][d];
            acc[i][0] = fmaf(ev, kv.x, acc[i][0]);
            acc[i][1] = fmaf(ev, kv.y, acc[i][1]);
            acc[i][2] = fmaf(ev, kv.z, acc[i][2]);
            acc[i][3] = fmaf(ev, kv.w, acc[i][3]);
        }
    }

    __half* Wr = d_W16 + (size_t)r * NN * OO;
#pragma unroll
    for (int i = 0; i < 8; i++) {
        int n = n0 + ng * 8 + i;
        __half2 h0 = __floats2half2_rn(acc[i][0], acc[i][1]);
        __half2 h1 = __floats2half2_rn(acc[i][2], acc[i][3]);
        __half2* p = (__half2*)(Wr + (size_t)n * OO + og * 4);
        p[0] = h0; p[1] = h1;
    }
}

// ---------------------------------------------------------------------------
// Kernel 3: main gathered GEMM. C[m, o] += sum_n adj[r, idx[m], n] * W[r][n][o]
// Tile: 128x128, K-chunk 64, one relation per CTA, atomicAdd epilogue.
// grid: (32 m-tiles, 8 relations, 2 branches), 256 threads (8 warps = 2x4)
// ---------------------------------------------------------------------------
#define BM 128
#define BK 64
#define ASTR (BK + 8)    // 72 halves / row
#define BSTR (OO + 8)    // 136 halves / row

__device__ __forceinline__ uint32_t smaddr(const void* p) {
    return (uint32_t)__cvta_generic_to_shared(p);
}
__device__ __forceinline__ void ldsm_x4(uint32_t (&r)[4], uint32_t addr) {
    asm volatile("ldmatrix.sync.aligned.m8n8.x4.shared.b16 {%0,%1,%2,%3}, [%4];"
        : "=r"(r[0]), "=r"(r[1]), "=r"(r[2]), "=r"(r[3]) : "r"(addr));
}
__device__ __forceinline__ void ldsm_x2t(uint32_t (&r)[2], uint32_t addr) {
    asm volatile("ldmatrix.sync.aligned.m8n8.x2.trans.shared.b16 {%0,%1}, [%2];"
        : "=r"(r[0]), "=r"(r[1]) : "r"(addr));
}
__device__ __forceinline__ void mma_16816(float (&c)[4], const uint32_t (&a)[4],
                                          const uint32_t (&b)[2]) {
    asm volatile(
        "mma.sync.aligned.m16n8k16.row.col.f32.f16.f16.f32 "
        "{%0,%1,%2,%3}, {%4,%5,%6,%7}, {%8,%9}, {%0,%1,%2,%3};"
        : "+f"(c[0]), "+f"(c[1]), "+f"(c[2]), "+f"(c[3])
        : "r"(a[0]), "r"(a[1]), "r"(a[2]), "r"(a[3]), "r"(b[0]), "r"(b[1]));
}

__global__ __launch_bounds__(256) void rgcn_main(
    const float* __restrict__ adj,
    const int* __restrict__ head_idx, const int* __restrict__ tail_idx,
    float* __restrict__ out)
{
    __shared__ __half As[BM * ASTR];   // 18432 B
    __shared__ __half Bs[BK * BSTR];   // 17408 B
    __shared__ int rows_s[BM];

    const int t = threadIdx.x;
    const int m0 = blockIdx.x * BM;
    const int r = blockIdx.y;
    const int branch = blockIdx.z;
    const int* idx = branch ? tail_idx : head_idx;

    if (t < BM) rows_s[t] = idx[m0 + t];
    __syncthreads();

    const float* adj_r = adj + (size_t)r * NN * NN;
    const __half* Wr = d_W16 + (size_t)r * NN * OO;

    // Per-thread gmem/smem slots. A: 2048 float4 per stage -> 8/thread.
    const float* aptr[8];
    __half* asst[8];
#pragma unroll
    for (int j = 0; j < 8; j++) {
        int id = t + j * 256;
        int arow = id >> 4, ac4 = id & 15;
        aptr[j] = adj_r + (size_t)rows_s[arow] * NN + ac4 * 4;
        asst[j] = &As[arow * ASTR + ac4 * 4];
    }
    // B: 1024 x 16B per stage -> 4/thread. Bs rows are k (W's n), o contiguous.
    const __half* bptr[4];
    __half* bsst[4];
#pragma unroll
    for (int j = 0; j < 4; j++) {
        int id = t + j * 256;
        int brow = id >> 4, bc8 = id & 15;
        bptr[j] = Wr + (size_t)brow * OO + bc8 * 8;
        bsst[j] = &Bs[brow * BSTR + bc8 * 8];
    }

    const int warp = t >> 5, lane = t & 31;
    const int wm = warp >> 2;            // 0..1 -> 64 M rows
    const int wn = warp & 3;             // 0..3 -> 32 N cols

    float acc[4][4][4];
#pragma unroll
    for (int mf = 0; mf < 4; mf++)
#pragma unroll
        for (int nf = 0; nf < 4; nf++)
#pragma unroll
            for (int v = 0; v < 4; v++) acc[mf][nf][v] = 0.f;

    // ldmatrix base addresses (ks = 0)
    uint32_t a_base[4], b_base[4];
#pragma unroll
    for (int mf = 0; mf < 4; mf++) {
        int row = wm * 64 + mf * 16 + (lane & 15);
        int col = ((lane >> 4) << 3);
        a_base[mf] = smaddr(&As[row * ASTR + col]);
    }
#pragma unroll
    for (int nf = 0; nf < 4; nf++) {
        int row = (lane & 15);
        int col = wn * 32 + nf * 8;
        b_base[nf] = smaddr(&Bs[row * BSTR + col]);
    }

    float4 areg[8];
    uint4 breg[4];

    auto LOAD = [&](int k0) {
#pragma unroll
        for (int j = 0; j < 8; j++) areg[j] = *(const float4*)(aptr[j] + k0);
#pragma unroll
        for (int j = 0; j < 4; j++)
            breg[j] = *(const uint4*)(bptr[j] + (size_t)k0 * OO);
    };
    auto STORE = [&]() {
#pragma unroll
        for (int j = 0; j < 8; j++) {
            __half2 h0 = __floats2half2_rn(areg[j].x, areg[j].y);
            __half2 h1 = __floats2half2_rn(areg[j].z, areg[j].w);
            ((__half2*)asst[j])[0] = h0;
            ((__half2*)asst[j])[1] = h1;
        }
#pragma unroll
        for (int j = 0; j < 4; j++) *(uint4*)bsst[j] = breg[j];
    };

    LOAD(0);
    STORE();
    __syncthreads();

    const int KITERS = NN / BK;          // 64
    for (int kt = 1; kt <= KITERS; kt++) {
        if (kt < KITERS) LOAD(kt * BK);  // prefetch next chunk into regs

#pragma unroll
        for (int ks = 0; ks < 4; ks++) { // 4 x k16 per chunk
            uint32_t af[4][4], bf[4][2];
#pragma unroll
            for (int mf = 0; mf < 4; mf++)
                ldsm_x4(af[mf], a_base[mf] + ks * 16 * 2);
#pragma unroll
            for (int nf = 0; nf < 4; nf++)
                ldsm_x2t(bf[nf], b_base[nf] + ks * 16 * BSTR * 2);
#pragma unroll
            for (int mf = 0; mf < 4; mf++)
#pragma unroll
                for (int nf = 0; nf < 4; nf++)
                    mma_16816(acc[mf][nf], af[mf], bf[nf]);
        }
        __syncthreads();
        if (kt < KITERS) {
            STORE();
            __syncthreads();
        }
    }

    // Epilogue: accumulate partial (this relation) into output
    float* ob = out + (size_t)branch * BB * OO;
    const int rbase = m0 + wm * 64 + (lane >> 2);
    const int cbase = wn * 32 + (lane & 3) * 2;
#pragma unroll
    for (int mf = 0; mf < 4; mf++) {
#pragma unroll
        for (int nf = 0; nf < 4; nf++) {
            int rr = rbase + mf * 16;
            int cc = cbase + nf * 8;
            atomicAdd(&ob[(size_t)rr * OO + cc],       acc[mf][nf][0]);
            atomicAdd(&ob[(size_t)rr * OO + cc + 1],   acc[mf][nf][1]);
            atomicAdd(&ob[(size_t)(rr + 8) * OO + cc],     acc[mf][nf][2]);
            atomicAdd(&ob[(size_t)(rr + 8) * OO + cc + 1], acc[mf][nf][3]);
        }
    }
}

// ---------------------------------------------------------------------------
extern "C" void kernel_launch(void* const* d_in, const int* in_sizes, int n_in,
                              void* d_out, int out_size)
{
    const float* emb  = (const float*)d_in[0];
    const int*   hidx = (const int*)  d_in[1];
    const float* he   = (const float*)d_in[2];
    const int*   tidx = (const int*)  d_in[3];
    const float* te   = (const float*)d_in[4];
    const float* adj  = (const float*)d_in[5];
    const float* relk = (const float*)d_in[6];
    const float* sk   = (const float*)d_in[7];
    float* out = (float*)d_out;

    // 1) base: out = e @ self_kernel (writes every output element)
    init_kernel<<<dim3(BB / 32, 2), 256>>>(he, te, sk, out);
    // 2) W[r] = E @ K[r] in fp32, stored fp16
    w_kernel<<<dim3(NN / 64, RR), 256>>>(emb, relk);
    // 3) gathered fp16 tensor-core GEMM, accumulated into out
    rgcn_main<<<dim3(NN / BM, RR, 2), 256>>>(adj, hidx, tidx, out);
}

// round 2
// speedup vs baseline: 1.5185x; 1.5185x over previous
#include <cuda_runtime.h>
#include <cuda_fp16.h>
#include <cstdint>

#define NN 4096   // nodes
#define DD 128    // embed dim
#define RR 8      // relations
#define OO 128    // out dim
#define BB 4096   // batch

// Scratch: W[r][n][o] = (E @ K[r])[n][o], fp16, 8 MB.
__device__ __half d_W16[RR * (size_t)NN * OO];
// Scratch: S[n][o] = sum_r (adj_r @ W_r)[n][o], fp32, 2 MB.
__device__ float d_S[(size_t)NN * OO];

// ---------------------------------------------------------------------------
// Kernel 0: zero S
// ---------------------------------------------------------------------------
__global__ __launch_bounds__(256) void zero_kernel()
{
    int i = blockIdx.x * 256 + threadIdx.x;
    ((float4*)d_S)[i] = make_float4(0.f, 0.f, 0.f, 0.f);
}

// ---------------------------------------------------------------------------
// Kernel 1: W16[r][n][o] = (E @ K[r])[n][o], fp32 accumulate, fp16 store
// grid: (64 n-tiles, 8 relations), 256 threads
// ---------------------------------------------------------------------------
__global__ __launch_bounds__(256) void w_kernel(
    const float* __restrict__ emb, const float* __restrict__ relk)
{
    __shared__ float Es[64][DD];                    // 32 KB
    const int t = threadIdx.x;
    const int n0 = blockIdx.x * 64;
    const int r = blockIdx.y;

#pragma unroll
    for (int j = 0; j < 8; j++) {
        int id = t + j * 256;
        int row = id >> 5, c = id & 31;
        *(float4*)&Es[row][c * 4] =
            *(const float4*)(emb + (size_t)(n0 + row) * DD + c * 4);
    }
    __syncthreads();

    const int og = t & 31;                          // o = og*4 .. +3
    const int ng = t >> 5;                          // rows ng*8 .. +7
    const float* Kr = relk + (size_t)r * DD * OO;

    float acc[8][4];
#pragma unroll
    for (int i = 0; i < 8; i++)
#pragma unroll
        for (int j = 0; j < 4; j++) acc[i][j] = 0.f;

    for (int d = 0; d < DD; d++) {
        float4 kv = *((const float4*)(Kr + (size_t)d * OO) + og);
#pragma unroll
        for (int i = 0; i < 8; i++) {
            float ev = Es[ng * 8 + i][d];
            acc[i][0] = fmaf(ev, kv.x, acc[i][0]);
            acc[i][1] = fmaf(ev, kv.y, acc[i][1]);
            acc[i][2] = fmaf(ev, kv.z, acc[i][2]);
            acc[i][3] = fmaf(ev, kv.w, acc[i][3]);
        }
    }

    __half* Wr = d_W16 + (size_t)r * NN * OO;
#pragma unroll
    for (int i = 0; i < 8; i++) {
        int n = n0 + ng * 8 + i;
        __half2 h0 = __floats2half2_rn(acc[i][0], acc[i][1]);
        __half2 h1 = __floats2half2_rn(acc[i][2], acc[i][3]);
        __half2* p = (__half2*)(Wr + (size_t)n * OO + og * 4);
        p[0] = h0; p[1] = h1;
    }
}

// ---------------------------------------------------------------------------
// Kernel 2: S[n, o] += sum_k adj[r, n0+n, kbase+k] * W[r][kbase+k][o]
// Tile: 128x128, K-chunk 64, one (m-tile, relation, K-half) per CTA.
// grid: (32 m-tiles, 8 relations, 2 K-halves), 256 threads (8 warps = 2x4)
// ---------------------------------------------------------------------------
#define BM 128
#define BK 64
#define KSPLIT 2
#define KHALF (NN / KSPLIT)   // 2048
#define ASTR (BK + 8)    // 72 halves / row
#define BSTR (OO + 8)    // 136 halves / row

__device__ __forceinline__ uint32_t smaddr(const void* p) {
    return (uint32_t)__cvta_generic_to_shared(p);
}
__device__ __forceinline__ void ldsm_x4(uint32_t (&r)[4], uint32_t addr) {
    asm volatile("ldmatrix.sync.aligned.m8n8.x4.shared.b16 {%0,%1,%2,%3}, [%4];"
        : "=r"(r[0]), "=r"(r[1]), "=r"(r[2]), "=r"(r[3]) : "r"(addr));
}
__device__ __forceinline__ void ldsm_x2t(uint32_t (&r)[2], uint32_t addr) {
    asm volatile("ldmatrix.sync.aligned.m8n8.x2.trans.shared.b16 {%0,%1}, [%2];"
        : "=r"(r[0]), "=r"(r[1]) : "r"(addr));
}
__device__ __forceinline__ void mma_16816(float (&c)[4], const uint32_t (&a)[4],
                                          const uint32_t (&b)[2]) {
    asm volatile(
        "mma.sync.aligned.m16n8k16.row.col.f32.f16.f16.f32 "
        "{%0,%1,%2,%3}, {%4,%5,%6,%7}, {%8,%9}, {%0,%1,%2,%3};"
        : "+f"(c[0]), "+f"(c[1]), "+f"(c[2]), "+f"(c[3])
        : "r"(a[0]), "r"(a[1]), "r"(a[2]), "r"(a[3]), "r"(b[0]), "r"(b[1]));
}

__global__ __launch_bounds__(256) void s_gemm(const float* __restrict__ adj)
{
    __shared__ __half As[BM * ASTR];   // 18432 B
    __shared__ __half Bs[BK * BSTR];   // 17408 B

    const int t = threadIdx.x;
    const int m0 = blockIdx.x * BM;
    const int r = blockIdx.y;
    const int kbase = blockIdx.z * KHALF;

    const float* adj_r = adj + (size_t)r * NN * NN;
    const __half* Wr = d_W16 + (size_t)r * NN * OO;

    // Per-thread gmem/smem slots. A: 2048 float4 per stage -> 8/thread.
    const float* aptr[8];
    __half* asst[8];
#pragma unroll
    for (int j = 0; j < 8; j++) {
        int id = t + j * 256;
        int arow = id >> 4, ac4 = id & 15;
        aptr[j] = adj_r + (size_t)(m0 + arow) * NN + kbase + ac4 * 4;
        asst[j] = &As[arow * ASTR + ac4 * 4];
    }
    // B: 1024 x 16B per stage -> 4/thread. Bs rows are k, o contiguous.
    const __half* bptr[4];
    __half* bsst[4];
#pragma unroll
    for (int j = 0; j < 4; j++) {
        int id = t + j * 256;
        int brow = id >> 4, bc8 = id & 15;
        bptr[j] = Wr + (size_t)(kbase + brow) * OO + bc8 * 8;
        bsst[j] = &Bs[brow * BSTR + bc8 * 8];
    }

    const int warp = t >> 5, lane = t & 31;
    const int wm = warp >> 2;            // 0..1 -> 64 M rows
    const int wn = warp & 3;             // 0..3 -> 32 N cols

    float acc[4][4][4];
#pragma unroll
    for (int mf = 0; mf < 4; mf++)
#pragma unroll
        for (int nf = 0; nf < 4; nf++)
#pragma unroll
            for (int v = 0; v < 4; v++) acc[mf][nf][v] = 0.f;

    uint32_t a_base[4], b_base[4];
#pragma unroll
    for (int mf = 0; mf < 4; mf++) {
        int row = wm * 64 + mf * 16 + (lane & 15);
        int col = ((lane >> 4) << 3);
        a_base[mf] = smaddr(&As[row * ASTR + col]);
    }
#pragma unroll
    for (int nf = 0; nf < 4; nf++) {
        int row = (lane & 15);
        int col = wn * 32 + nf * 8;
        b_base[nf] = smaddr(&Bs[row * BSTR + col]);
    }

    float4 areg[8];
    uint4 breg[4];

    auto LOAD = [&](int k0) {
#pragma unroll
        for (int j = 0; j < 8; j++) areg[j] = *(const float4*)(aptr[j] + k0);
#pragma unroll
        for (int j = 0; j < 4; j++)
            breg[j] = *(const uint4*)(bptr[j] + (size_t)k0 * OO);
    };
    auto STORE = [&]() {
#pragma unroll
        for (int j = 0; j < 8; j++) {
            __half2 h0 = __floats2half2_rn(areg[j].x, areg[j].y);
            __half2 h1 = __floats2half2_rn(areg[j].z, areg[j].w);
            ((__half2*)asst[j])[0] = h0;
            ((__half2*)asst[j])[1] = h1;
        }
#pragma unroll
        for (int j = 0; j < 4; j++) *(uint4*)bsst[j] = breg[j];
    };

    LOAD(0);
    STORE();
    __syncthreads();

    const int KITERS = KHALF / BK;       // 32
    for (int kt = 1; kt <= KITERS; kt++) {
        if (kt < KITERS) LOAD(kt * BK);  // prefetch next chunk into regs

#pragma unroll
        for (int ks = 0; ks < 4; ks++) { // 4 x k16 per chunk
            uint32_t af[4][4], bf[4][2];
#pragma unroll
            for (int mf = 0; mf < 4; mf++)
                ldsm_x4(af[mf], a_base[mf] + ks * 16 * 2);
#pragma unroll
            for (int nf = 0; nf < 4; nf++)
                ldsm_x2t(bf[nf], b_base[nf] + ks * 16 * BSTR * 2);
#pragma unroll
            for (int mf = 0; mf < 4; mf++)
#pragma unroll
                for (int nf = 0; nf < 4; nf++)
                    mma_16816(acc[mf][nf], af[mf], bf[nf]);
        }
        __syncthreads();
        if (kt < KITERS) {
            STORE();
            __syncthreads();
        }
    }

    // Epilogue: accumulate this (relation, K-half) partial into S
    const int rbase = m0 + wm * 64 + (lane >> 2);
    const int cbase = wn * 32 + (lane & 3) * 2;
#pragma unroll
    for (int mf = 0; mf < 4; mf++) {
#pragma unroll
        for (int nf = 0; nf < 4; nf++) {
            int rr = rbase + mf * 16;
            int cc = cbase + nf * 8;
            atomicAdd(&d_S[(size_t)rr * OO + cc],           acc[mf][nf][0]);
            atomicAdd(&d_S[(size_t)rr * OO + cc + 1],       acc[mf][nf][1]);
            atomicAdd(&d_S[(size_t)(rr + 8) * OO + cc],     acc[mf][nf][2]);
            atomicAdd(&d_S[(size_t)(rr + 8) * OO + cc + 1], acc[mf][nf][3]);
        }
    }
}

// ---------------------------------------------------------------------------
// Kernel 3: out[branch][m][o] = (e @ self_kernel)[m][o] + S[idx[m]][o]
// grid: (128 row-tiles of 32, 2 branches), 256 threads
// ---------------------------------------------------------------------------
__global__ __launch_bounds__(256) void final_kernel(
    const float* __restrict__ head_e, const float* __restrict__ tail_e,
    const int* __restrict__ head_idx, const int* __restrict__ tail_idx,
    const float* __restrict__ sk, float* __restrict__ out)
{
    __shared__ float Es[32][DD];                    // 16 KB
    __shared__ int idxs[32];
    const int t = threadIdx.x;
    const int n0 = blockIdx.x * 32;
    const int branch = blockIdx.y;
    const float* e = branch ? tail_e : head_e;
    const int* idx = branch ? tail_idx : head_idx;

#pragma unroll
    for (int j = 0; j < 4; j++) {
        int id = t + j * 256;
        int row = id >> 5, c = id & 31;
        *(float4*)&Es[row][c * 4] =
            *(const float4*)(e + (size_t)(n0 + row) * DD + c * 4);
    }
    if (t < 32) idxs[t] = idx[n0 + t];
    __syncthreads();

    const int o = t & 127;
    const int hf = t >> 7;                          // 0..1 -> 16 rows each
    float acc[16];
#pragma unroll
    for (int i = 0; i < 16; i++) acc[i] = 0.f;

#pragma unroll 4
    for (int d4 = 0; d4 < DD / 4; d4++) {
        float s0 = sk[(d4 * 4 + 0) * OO + o];
        float s1 = sk[(d4 * 4 + 1) * OO + o];
        float s2 = sk[(d4 * 4 + 2) * OO + o];
        float s3 = sk[(d4 * 4 + 3) * OO + o];
#pragma unroll
        for (int i = 0; i < 16; i++) {
            float4 ev = *(float4*)&Es[hf * 16 + i][d4 * 4];
            acc[i] = fmaf(ev.x, s0, acc[i]);
            acc[i] = fmaf(ev.y, s1, acc[i]);
            acc[i] = fmaf(ev.z, s2, acc[i]);
            acc[i] = fmaf(ev.w, s3, acc[i]);
        }
    }

    float* ob = out + (size_t)branch * BB * OO;
#pragma unroll
    for (int i = 0; i < 16; i++) {
        int row = hf * 16 + i;
        float sv = d_S[(size_t)idxs[row] * OO + o];
        ob[(size_t)(n0 + row) * OO + o] = acc[i] + sv;
    }
}

// ---------------------------------------------------------------------------
extern "C" void kernel_launch(void* const* d_in, const int* in_sizes, int n_in,
                              void* d_out, int out_size)
{
    const float* emb  = (const float*)d_in[0];
    const int*   hidx = (const int*)  d_in[1];
    const float* he   = (const float*)d_in[2];
    const int*   tidx = (const int*)  d_in[3];
    const float* te   = (const float*)d_in[4];
    const float* adj  = (const float*)d_in[5];
    const float* relk = (const float*)d_in[6];
    const float* sk   = (const float*)d_in[7];
    float* out = (float*)d_out;

    // 0) S = 0
    zero_kernel<<<NN * OO / (256 * 4), 256>>>();
    // 1) W[r] = E @ K[r] in fp32, stored fp16
    w_kernel<<<dim3(NN / 64, RR), 256>>>(emb, relk);
    // 2) S = sum_r adj_r @ W_r   (fp16 tensor-core GEMM, atomic accumulate)
    s_gemm<<<dim3(NN / BM, RR, KSPLIT), 256>>>(adj);
    // 3) out = e @ self_kernel + gather(S, idx)
    final_kernel<<<dim3(BB / 32, 2), 256>>>(he, te, hidx, tidx, sk, out);
}